// round 1
// baseline (speedup 1.0000x reference)
#include <cuda_runtime.h>
#include <cuda_bf16.h>
#include <math.h>

// Problem constants
#define NB   2
#define C    256
#define H    64
#define W    64
#define HW   4096
#define M    8192          // NB*H*W pixels
#define G    8
#define P    9
#define CG   32
#define OMC  216           // 144 offsets + 72 mask logits per pixel

// Scratch (device globals; no allocation allowed)
__device__ float g_y[M * C];       // conv1+bn+silu, NHWC
__device__ float g_xproj[M * C];   // input proj, NHWC
__device__ float g_z[M * C];       // dw+ln+gelu, NHWC
__device__ float g_om[M * OMC];    // offsets(144) + mask logits(72)
__device__ float g_s[M * C];       // sampled output, NHWC

// ---------------------------------------------------------------------------
// Kernel 1: y = SiLU(BN1(x @ conv1_w^T))  ; x is NCHW, out NHWC
// GEMM: out[p][o] = sum_c x[n,c,hw] * w1[o*C+c]
// 64x64 tile, BK=16, 16x16 threads, 4x4 per thread. tx->o, ty->p.
// ---------------------------------------------------------------------------
__global__ __launch_bounds__(256) void conv1_kernel(
    const float* __restrict__ x, const float* __restrict__ w1,
    const float* __restrict__ bg, const float* __restrict__ bb,
    const float* __restrict__ bm, const float* __restrict__ bv,
    float* __restrict__ out)
{
    __shared__ float As[16][65];
    __shared__ float Bs[16][65];
    const int bo = blockIdx.x * 64;
    const int bp = blockIdx.y * 64;
    const int tx = threadIdx.x, ty = threadIdx.y;
    const int tid = ty * 16 + tx;
    const int n = bp >> 12;
    const int hwb = bp & 4095;
    const float* xb = x + (size_t)n * C * HW + hwb;

    float acc[4][4] = {};
    for (int k0 = 0; k0 < C; k0 += 16) {
        // As[c][p] = x[n, k0+c, hwb+p]   (coalesced over p)
        #pragma unroll
        for (int r = 0; r < 4; r++) {
            int c = r * 4 + (tid >> 6);
            int p = tid & 63;
            As[c][p] = xb[(k0 + c) * HW + p];
        }
        // Bs[c][o] = w1[(bo+o)*C + k0+c]  (coalesced over c)
        #pragma unroll
        for (int r = 0; r < 4; r++) {
            int o = r * 16 + (tid >> 4);
            int c = tid & 15;
            Bs[c][o] = w1[(bo + o) * C + k0 + c];
        }
        __syncthreads();
        #pragma unroll
        for (int kk = 0; kk < 16; kk++) {
            float a[4], b[4];
            #pragma unroll
            for (int i = 0; i < 4; i++) a[i] = As[kk][ty * 4 + i];
            #pragma unroll
            for (int j = 0; j < 4; j++) b[j] = Bs[kk][tx * 4 + j];
            #pragma unroll
            for (int i = 0; i < 4; i++)
                #pragma unroll
                for (int j = 0; j < 4; j++) acc[i][j] += a[i] * b[j];
        }
        __syncthreads();
    }
    // epilogue: BN(eps=1e-3) + SiLU, write NHWC (float4 over o)
    float sc[4], bi[4];
    #pragma unroll
    for (int j = 0; j < 4; j++) {
        int o = bo + tx * 4 + j;
        sc[j] = bg[o] * rsqrtf(bv[o] + 1e-3f);
        bi[j] = bb[o] - bm[o] * sc[j];
    }
    #pragma unroll
    for (int i = 0; i < 4; i++) {
        int p = bp + ty * 4 + i;
        float4 v;
        float t0 = acc[i][0] * sc[0] + bi[0];
        float t1 = acc[i][1] * sc[1] + bi[1];
        float t2 = acc[i][2] * sc[2] + bi[2];
        float t3 = acc[i][3] * sc[3] + bi[3];
        v.x = t0 / (1.f + __expf(-t0));
        v.y = t1 / (1.f + __expf(-t1));
        v.z = t2 / (1.f + __expf(-t2));
        v.w = t3 / (1.f + __expf(-t3));
        *reinterpret_cast<float4*>(&out[(size_t)p * C + bo + tx * 4]) = v;
    }
}

// ---------------------------------------------------------------------------
// Kernel 2: xproj = y @ inproj_w + b    (both NHWC row-major). tx->o, ty->p.
// ---------------------------------------------------------------------------
__global__ __launch_bounds__(256) void inproj_kernel(
    const float* __restrict__ A, const float* __restrict__ Wm,
    const float* __restrict__ bias, float* __restrict__ out)
{
    __shared__ float As[16][65];
    __shared__ float Bs[16][65];
    const int bo = blockIdx.x * 64;
    const int bp = blockIdx.y * 64;
    const int tx = threadIdx.x, ty = threadIdx.y;
    const int tid = ty * 16 + tx;

    float acc[4][4] = {};
    for (int k0 = 0; k0 < C; k0 += 16) {
        #pragma unroll
        for (int r = 0; r < 4; r++) {          // As[c][p] = A[(bp+p)*C + k0+c]
            int p = r * 16 + (tid >> 4);
            int c = tid & 15;
            As[c][p] = A[(size_t)(bp + p) * C + k0 + c];
        }
        #pragma unroll
        for (int r = 0; r < 4; r++) {          // Bs[c][o] = Wm[(k0+c)*C + bo+o]
            int c = r * 4 + (tid >> 6);
            int o = tid & 63;
            Bs[c][o] = Wm[(size_t)(k0 + c) * C + bo + o];
        }
        __syncthreads();
        #pragma unroll
        for (int kk = 0; kk < 16; kk++) {
            float a[4], b[4];
            #pragma unroll
            for (int i = 0; i < 4; i++) a[i] = As[kk][ty * 4 + i];
            #pragma unroll
            for (int j = 0; j < 4; j++) b[j] = Bs[kk][tx * 4 + j];
            #pragma unroll
            for (int i = 0; i < 4; i++)
                #pragma unroll
                for (int j = 0; j < 4; j++) acc[i][j] += a[i] * b[j];
        }
        __syncthreads();
    }
    float bi[4];
    #pragma unroll
    for (int j = 0; j < 4; j++) bi[j] = bias[bo + tx * 4 + j];
    #pragma unroll
    for (int i = 0; i < 4; i++) {
        int p = bp + ty * 4 + i;
        float4 v = make_float4(acc[i][0] + bi[0], acc[i][1] + bi[1],
                               acc[i][2] + bi[2], acc[i][3] + bi[3]);
        *reinterpret_cast<float4*>(&out[(size_t)p * C + bo + tx * 4]) = v;
    }
}

// ---------------------------------------------------------------------------
// Kernel 3: depthwise 3x3 conv(+bias) on y -> LayerNorm over C -> GELU(exact)
// one block (256 thr) per pixel
// ---------------------------------------------------------------------------
__global__ __launch_bounds__(256) void dwln_kernel(
    const float* __restrict__ y, const float* __restrict__ dww,
    const float* __restrict__ dwb, const float* __restrict__ lng,
    const float* __restrict__ lnb, float* __restrict__ z)
{
    const int p = blockIdx.x;
    const int c = threadIdx.x;
    const int n = p >> 12, hw = p & 4095;
    const int h = hw >> 6, w = hw & 63;

    float acc = dwb[c];
    #pragma unroll
    for (int ky = 0; ky < 3; ky++) {
        int hh = h + ky - 1;
        if (hh < 0 || hh > 63) continue;
        #pragma unroll
        for (int kx = 0; kx < 3; kx++) {
            int ww = w + kx - 1;
            if (ww < 0 || ww > 63) continue;
            acc += y[((size_t)(n << 12) + (hh << 6) + ww) * C + c] * dww[c * 9 + ky * 3 + kx];
        }
    }
    // block LN over 256 channels
    float s1 = acc, s2 = acc * acc;
    #pragma unroll
    for (int o = 16; o; o >>= 1) {
        s1 += __shfl_xor_sync(0xffffffffu, s1, o);
        s2 += __shfl_xor_sync(0xffffffffu, s2, o);
    }
    __shared__ float w1[8], w2[8];
    int warp = c >> 5, lane = c & 31;
    if (lane == 0) { w1[warp] = s1; w2[warp] = s2; }
    __syncthreads();
    if (warp == 0) {
        float a = lane < 8 ? w1[lane] : 0.f;
        float b = lane < 8 ? w2[lane] : 0.f;
        #pragma unroll
        for (int o = 4; o; o >>= 1) {
            a += __shfl_xor_sync(0xffffffffu, a, o);
            b += __shfl_xor_sync(0xffffffffu, b, o);
        }
        if (lane == 0) { w1[0] = a; w2[0] = b; }
    }
    __syncthreads();
    float mu = w1[0] * (1.f / 256.f);
    float var = w2[0] * (1.f / 256.f) - mu * mu;
    float zn = (acc - mu) * rsqrtf(var + 1e-5f) * lng[c] + lnb[c];
    float gl = 0.5f * zn * (1.f + erff(zn * 0.70710678118654752f));
    z[(size_t)p * C + c] = gl;
}

// ---------------------------------------------------------------------------
// Kernel 4: om = z @ [off_w | mask_w] + [off_b | mask_b]   (216 cols)
// ---------------------------------------------------------------------------
__global__ __launch_bounds__(256) void offmask_kernel(
    const float* __restrict__ A, const float* __restrict__ offw,
    const float* __restrict__ offb, const float* __restrict__ maskw,
    const float* __restrict__ maskb, float* __restrict__ out)
{
    __shared__ float As[16][65];
    __shared__ float Bs[16][65];
    const int bo = blockIdx.x * 64;
    const int bp = blockIdx.y * 64;
    const int tx = threadIdx.x, ty = threadIdx.y;
    const int tid = ty * 16 + tx;

    float acc[4][4] = {};
    for (int k0 = 0; k0 < C; k0 += 16) {
        #pragma unroll
        for (int r = 0; r < 4; r++) {
            int p = r * 16 + (tid >> 4);
            int c = tid & 15;
            As[c][p] = A[(size_t)(bp + p) * C + k0 + c];
        }
        #pragma unroll
        for (int r = 0; r < 4; r++) {
            int c = r * 4 + (tid >> 6);
            int o = tid & 63;
            int col = bo + o;
            float v = 0.f;
            if (col < 144)      v = offw[(size_t)(k0 + c) * 144 + col];
            else if (col < 216) v = maskw[(size_t)(k0 + c) * 72 + (col - 144)];
            Bs[c][o] = v;
        }
        __syncthreads();
        #pragma unroll
        for (int kk = 0; kk < 16; kk++) {
            float a[4], b[4];
            #pragma unroll
            for (int i = 0; i < 4; i++) a[i] = As[kk][ty * 4 + i];
            #pragma unroll
            for (int j = 0; j < 4; j++) b[j] = Bs[kk][tx * 4 + j];
            #pragma unroll
            for (int i = 0; i < 4; i++)
                #pragma unroll
                for (int j = 0; j < 4; j++) acc[i][j] += a[i] * b[j];
        }
        __syncthreads();
    }
    #pragma unroll
    for (int j = 0; j < 4; j++) {
        int o = bo + tx * 4 + j;
        if (o >= OMC) continue;
        float bi = (o < 144) ? offb[o] : maskb[o - 144];
        #pragma unroll
        for (int i = 0; i < 4; i++) {
            int p = bp + ty * 4 + i;
            out[(size_t)p * OMC + o] = acc[i][j] + bi;
        }
    }
}

// ---------------------------------------------------------------------------
// Kernel 5: deformable sampling. Block = pixel (256 thr), warp = group.
// s[p, g*32+lane] = sum_p9 softmax(mask)[p9] * bilinear(xproj, loc)
// Padded coords: loc_x = w + (i/3) + off_x ; valid data iff coord in [1,64].
// ---------------------------------------------------------------------------
__device__ __forceinline__ float samp(const float* __restrict__ xb, int yy, int xx)
{
    if (yy >= 1 && yy <= 64 && xx >= 1 && xx <= 64)
        return xb[((size_t)((yy - 1) << 6) + (xx - 1)) * C];
    return 0.f;
}

__global__ __launch_bounds__(256) void dcn_kernel(
    const float* __restrict__ xproj, const float* __restrict__ om,
    float* __restrict__ s)
{
    const int p = blockIdx.x;
    const int t = threadIdx.x;
    const int g = t >> 5, lane = t & 31;
    const int n = p >> 12, hw = p & 4095;
    const int h = hw >> 6, w = hw & 63;

    const float* offp = om + (size_t)p * OMC + g * 18;
    const float* mlp  = om + (size_t)p * OMC + 144 + g * 9;

    float ml[9];
    float mx = -1e30f;
    #pragma unroll
    for (int i = 0; i < 9; i++) { ml[i] = mlp[i]; mx = fmaxf(mx, ml[i]); }
    float se = 0.f;
    #pragma unroll
    for (int i = 0; i < 9; i++) { ml[i] = expf(ml[i] - mx); se += ml[i]; }
    float inv = 1.f / se;

    const int ch = g * 32 + lane;
    const float* xb = xproj + (size_t)n * HW * C + ch;
    float acc = 0.f;
    #pragma unroll
    for (int i = 0; i < 9; i++) {
        float px = (float)w + (float)(i / 3) + offp[2 * i];
        float py = (float)h + (float)(i % 3) + offp[2 * i + 1];
        float x0f = floorf(px), y0f = floorf(py);
        float wx = px - x0f, wy = py - y0f;
        int x0 = (int)x0f, y0 = (int)y0f;
        float v00 = samp(xb, y0,     x0);
        float v10 = samp(xb, y0,     x0 + 1);
        float v01 = samp(xb, y0 + 1, x0);
        float v11 = samp(xb, y0 + 1, x0 + 1);
        float bil = v00 * (1.f - wx) * (1.f - wy) + v10 * wx * (1.f - wy)
                  + v01 * (1.f - wx) * wy         + v11 * wx * wy;
        acc += ml[i] * inv * bil;
    }
    s[(size_t)p * C + ch] = acc;
}

// ---------------------------------------------------------------------------
// Kernel 6: out = SiLU(BN2(s @ outproj_w + b))  -> NCHW
// tx->p (coalesced NCHW writes), ty->o
// ---------------------------------------------------------------------------
__global__ __launch_bounds__(256) void outproj_kernel(
    const float* __restrict__ A, const float* __restrict__ Wm,
    const float* __restrict__ bias,
    const float* __restrict__ bg, const float* __restrict__ bb,
    const float* __restrict__ bm, const float* __restrict__ bv,
    float* __restrict__ out)
{
    __shared__ float As[16][65];
    __shared__ float Bs[16][65];
    const int bo = blockIdx.x * 64;
    const int bp = blockIdx.y * 64;
    const int tx = threadIdx.x, ty = threadIdx.y;
    const int tid = ty * 16 + tx;
    const int n = bp >> 12;
    const int hwb = bp & 4095;

    float acc[4][4] = {};   // [i over p][j over o]
    for (int k0 = 0; k0 < C; k0 += 16) {
        #pragma unroll
        for (int r = 0; r < 4; r++) {
            int p = r * 16 + (tid >> 4);
            int c = tid & 15;
            As[c][p] = A[(size_t)(bp + p) * C + k0 + c];
        }
        #pragma unroll
        for (int r = 0; r < 4; r++) {
            int c = r * 4 + (tid >> 6);
            int o = tid & 63;
            Bs[c][o] = Wm[(size_t)(k0 + c) * C + bo + o];
        }
        __syncthreads();
        #pragma unroll
        for (int kk = 0; kk < 16; kk++) {
            float a[4], b[4];
            #pragma unroll
            for (int i = 0; i < 4; i++) a[i] = As[kk][tx * 4 + i];   // p
            #pragma unroll
            for (int j = 0; j < 4; j++) b[j] = Bs[kk][ty * 4 + j];   // o
            #pragma unroll
            for (int i = 0; i < 4; i++)
                #pragma unroll
                for (int j = 0; j < 4; j++) acc[i][j] += a[i] * b[j];
        }
        __syncthreads();
    }
    #pragma unroll
    for (int j = 0; j < 4; j++) {
        int o = bo + ty * 4 + j;
        float sc = bg[o] * rsqrtf(bv[o] + 1e-5f);
        float bi = bb[o] - bm[o] * sc;
        float bs = bias[o];
        float4 v;
        float t0 = (acc[0][j] + bs) * sc + bi;
        float t1 = (acc[1][j] + bs) * sc + bi;
        float t2 = (acc[2][j] + bs) * sc + bi;
        float t3 = (acc[3][j] + bs) * sc + bi;
        v.x = t0 / (1.f + __expf(-t0));
        v.y = t1 / (1.f + __expf(-t1));
        v.z = t2 / (1.f + __expf(-t2));
        v.w = t3 / (1.f + __expf(-t3));
        *reinterpret_cast<float4*>(
            &out[((size_t)(n * C + o)) * HW + hwb + tx * 4]) = v;
    }
}

// ---------------------------------------------------------------------------
extern "C" void kernel_launch(void* const* d_in, const int* in_sizes, int n_in,
                              void* d_out, int out_size)
{
    const float* x        = (const float*)d_in[0];
    const float* conv1_w  = (const float*)d_in[1];
    const float* bn1_g    = (const float*)d_in[2];
    const float* bn1_b    = (const float*)d_in[3];
    const float* bn1_m    = (const float*)d_in[4];
    const float* bn1_v    = (const float*)d_in[5];
    const float* inproj_w = (const float*)d_in[6];
    const float* inproj_b = (const float*)d_in[7];
    const float* dw_w     = (const float*)d_in[8];
    const float* dw_b     = (const float*)d_in[9];
    const float* ln_g     = (const float*)d_in[10];
    const float* ln_b     = (const float*)d_in[11];
    const float* off_w    = (const float*)d_in[12];
    const float* off_b    = (const float*)d_in[13];
    const float* mask_w   = (const float*)d_in[14];
    const float* mask_b   = (const float*)d_in[15];
    const float* outproj_w= (const float*)d_in[16];
    const float* outproj_b= (const float*)d_in[17];
    const float* bn2_g    = (const float*)d_in[18];
    const float* bn2_b    = (const float*)d_in[19];
    const float* bn2_m    = (const float*)d_in[20];
    const float* bn2_v    = (const float*)d_in[21];
    float* out = (float*)d_out;

    float *y, *xproj, *z, *om, *s;
    cudaGetSymbolAddress((void**)&y,     g_y);
    cudaGetSymbolAddress((void**)&xproj, g_xproj);
    cudaGetSymbolAddress((void**)&z,     g_z);
    cudaGetSymbolAddress((void**)&om,    g_om);
    cudaGetSymbolAddress((void**)&s,     g_s);

    dim3 blk(16, 16);
    dim3 grd(C / 64, M / 64);      // (4, 128)

    conv1_kernel<<<grd, blk>>>(x, conv1_w, bn1_g, bn1_b, bn1_m, bn1_v, y);
    inproj_kernel<<<grd, blk>>>(y, inproj_w, inproj_b, xproj);
    dwln_kernel<<<M, 256>>>(y, dw_w, dw_b, ln_g, ln_b, z);
    offmask_kernel<<<dim3(4, M / 64), blk>>>(z, off_w, off_b, mask_w, mask_b, om);
    dcn_kernel<<<M, 256>>>(xproj, om, s);
    outproj_kernel<<<grd, blk>>>(s, outproj_w, outproj_b,
                                 bn2_g, bn2_b, bn2_m, bn2_v, out);
}

// round 2
// speedup vs baseline: 1.3059x; 1.3059x over previous
#include <cuda_runtime.h>
#include <cuda_bf16.h>
#include <math.h>

// Problem constants
#define NB   2
#define C    256
#define H    64
#define W    64
#define HW   4096
#define M    8192          // NB*H*W pixels
#define G    8
#define P    9
#define CG   32
#define OMC  216           // 144 offsets + 72 mask logits per pixel

// Scratch (device globals; no allocation allowed)
__device__ float g_y[M * C];       // conv1+bn+silu, NHWC
__device__ float g_xproj[M * C];   // input proj, NHWC
__device__ float g_z[M * C];       // dw+ln+gelu, NHWC
__device__ float g_om[M * OMC];    // offsets(144) + mask logits(72)
__device__ float g_s[M * C];       // sampled output, NHWC

typedef unsigned long long u64;

__device__ __forceinline__ u64 pk2(float lo, float hi) {
    u64 r; asm("mov.b64 %0,{%1,%2};" : "=l"(r) : "f"(lo), "f"(hi)); return r;
}
__device__ __forceinline__ void fma2(u64& d, u64 a, u64 b) {
    asm("fma.rn.f32x2 %0,%1,%2,%0;" : "+l"(d) : "l"(a), "l"(b));
}
__device__ __forceinline__ float2 up2(u64 v) {
    float lo, hi; asm("mov.b64 {%0,%1},%2;" : "=f"(lo), "=f"(hi) : "l"(v));
    return make_float2(lo, hi);
}
__device__ __forceinline__ float silu(float t) { return t / (1.f + __expf(-t)); }

// ---------------------------------------------------------------------------
// Unified 128x128x16 SGEMM with FFMA2 (fma.rn.f32x2), 256 threads, 8x8/thread.
// MODE 0: conv1  : A = x NCHW (K-major), B = w1[N][K] (transposed load),
//                  epi = BN1(1e-3)+SiLU, out NHWC
// MODE 1: inproj : A NHWC, B = W[K][N], epi = +bias, out NHWC
// MODE 2: offmask: A NHWC, B = [off_w | mask_w] (216 cols), epi = +bias, guard
// MODE 3: outproj: A NHWC, B = W[K][N], epi = +bias, BN2(1e-5)+SiLU, out NCHW
// ---------------------------------------------------------------------------
template<int MODE>
__global__ __launch_bounds__(256, 1)
void gemm_k(const float* __restrict__ A,
            const float* __restrict__ B0,
            const float* __restrict__ B1,
            const float* __restrict__ bias0,
            const float* __restrict__ bias1,
            const float* __restrict__ bg, const float* __restrict__ bb,
            const float* __restrict__ bm, const float* __restrict__ bv,
            float* __restrict__ out)
{
    __shared__ float As[16][128];
    __shared__ float Bs[16][128];
    const int bo = blockIdx.x * 128;
    const int bp = blockIdx.y * 128;
    const int tid = threadIdx.x;
    const int tx = tid & 15, ty = tid >> 4;

    float4 stA[2], stB[2];

    // ---- global load (stage into regs) ----
    auto loadA = [&](int k0) {
        if (MODE == 0) {
            // x NCHW: As[k][p] = x[n, k0+k, hwb+p]; coalesced float4 over p
            const int p4 = tid & 31, kk = tid >> 5;          // kk 0..7
            const int n = bp >> 12, hwb = (bp & 4095) + p4 * 4;
            const float* xb = A + (size_t)n * C * HW + hwb;
            stA[0] = *(const float4*)&xb[(size_t)(k0 + kk) * HW];
            stA[1] = *(const float4*)&xb[(size_t)(k0 + kk + 8) * HW];
        } else {
            // NHWC: per-thread one 32B k-chunk of one row
            const int lp = tid & 127, lk = (tid >> 7) * 8;   // lk 0 or 8
            const float* ab = A + (size_t)(bp + lp) * C + k0 + lk;
            stA[0] = *(const float4*)&ab[0];
            stA[1] = *(const float4*)&ab[4];
        }
    };
    auto storeA = [&]() {
        if (MODE == 0) {
            const int p4 = tid & 31, kk = tid >> 5;
            *(float4*)&As[kk][p4 * 4]     = stA[0];
            *(float4*)&As[kk + 8][p4 * 4] = stA[1];
        } else {
            const int lp = tid & 127, lk = (tid >> 7) * 8;
            As[lk + 0][lp] = stA[0].x; As[lk + 1][lp] = stA[0].y;
            As[lk + 2][lp] = stA[0].z; As[lk + 3][lp] = stA[0].w;
            As[lk + 4][lp] = stA[1].x; As[lk + 5][lp] = stA[1].y;
            As[lk + 6][lp] = stA[1].z; As[lk + 7][lp] = stA[1].w;
        }
    };
    auto loadB = [&](int k0) {
        if (MODE == 0) {
            // w1[N][K]: transpose load, per-thread 32B k-chunk of one out-row
            const int lo = tid & 127, lk = (tid >> 7) * 8;
            const float* wb = B0 + (size_t)(bo + lo) * C + k0 + lk;
            stB[0] = *(const float4*)&wb[0];
            stB[1] = *(const float4*)&wb[4];
        } else if (MODE == 2) {
            const int o4 = tid & 31, kk = tid >> 5;
            const int col = bo + o4 * 4;
            float4 z = make_float4(0.f, 0.f, 0.f, 0.f);
            stB[0] = z; stB[1] = z;
            if (col < 144) {
                stB[0] = *(const float4*)&B0[(size_t)(k0 + kk) * 144 + col];
                stB[1] = *(const float4*)&B0[(size_t)(k0 + kk + 8) * 144 + col];
            } else if (col < 216) {
                stB[0] = *(const float4*)&B1[(size_t)(k0 + kk) * 72 + col - 144];
                stB[1] = *(const float4*)&B1[(size_t)(k0 + kk + 8) * 72 + col - 144];
            }
        } else {
            const int o4 = tid & 31, kk = tid >> 5;
            stB[0] = *(const float4*)&B0[(size_t)(k0 + kk) * C + bo + o4 * 4];
            stB[1] = *(const float4*)&B0[(size_t)(k0 + kk + 8) * C + bo + o4 * 4];
        }
    };
    auto storeB = [&]() {
        if (MODE == 0) {
            const int lo = tid & 127, lk = (tid >> 7) * 8;
            Bs[lk + 0][lo] = stB[0].x; Bs[lk + 1][lo] = stB[0].y;
            Bs[lk + 2][lo] = stB[0].z; Bs[lk + 3][lo] = stB[0].w;
            Bs[lk + 4][lo] = stB[1].x; Bs[lk + 5][lo] = stB[1].y;
            Bs[lk + 6][lo] = stB[1].z; Bs[lk + 7][lo] = stB[1].w;
        } else {
            const int o4 = tid & 31, kk = tid >> 5;
            *(float4*)&Bs[kk][o4 * 4]     = stB[0];
            *(float4*)&Bs[kk + 8][o4 * 4] = stB[1];
        }
    };

    u64 acc[4][8];
    #pragma unroll
    for (int i = 0; i < 4; i++)
        #pragma unroll
        for (int j = 0; j < 8; j++) acc[i][j] = 0ull;

    loadA(0); loadB(0);
    storeA(); storeB();
    __syncthreads();

    #pragma unroll 1
    for (int t = 0; t < 16; t++) {
        if (t < 15) { loadA((t + 1) * 16); loadB((t + 1) * 16); }
        #pragma unroll
        for (int kk = 0; kk < 16; kk++) {
            float4 a0 = *(const float4*)&As[kk][ty * 8];
            float4 a1 = *(const float4*)&As[kk][ty * 8 + 4];
            float4 b0 = *(const float4*)&Bs[kk][tx * 8];
            float4 b1 = *(const float4*)&Bs[kk][tx * 8 + 4];
            u64 a2[4];
            a2[0] = pk2(a0.x, a0.y); a2[1] = pk2(a0.z, a0.w);
            a2[2] = pk2(a1.x, a1.y); a2[3] = pk2(a1.z, a1.w);
            float bf[8] = {b0.x, b0.y, b0.z, b0.w, b1.x, b1.y, b1.z, b1.w};
            #pragma unroll
            for (int j = 0; j < 8; j++) {
                u64 bd = pk2(bf[j], bf[j]);
                fma2(acc[0][j], a2[0], bd);
                fma2(acc[1][j], a2[1], bd);
                fma2(acc[2][j], a2[2], bd);
                fma2(acc[3][j], a2[3], bd);
            }
        }
        if (t < 15) { __syncthreads(); storeA(); storeB(); __syncthreads(); }
    }

    // unpack accumulators: r[i over p][j over o]
    float r[8][8];
    #pragma unroll
    for (int i2 = 0; i2 < 4; i2++)
        #pragma unroll
        for (int j = 0; j < 8; j++) {
            float2 v = up2(acc[i2][j]);
            r[2 * i2][j] = v.x; r[2 * i2 + 1][j] = v.y;
        }

    if (MODE == 0 || MODE == 1) {
        float sc[8], bi[8];
        #pragma unroll
        for (int j = 0; j < 8; j++) {
            int o = bo + tx * 8 + j;
            if (MODE == 0) {
                sc[j] = bg[o] * rsqrtf(bv[o] + 1e-3f);
                bi[j] = bb[o] - bm[o] * sc[j];
            } else { sc[j] = 1.f; bi[j] = bias0[o]; }
        }
        #pragma unroll
        for (int i = 0; i < 8; i++) {
            int p = bp + ty * 8 + i;
            float v[8];
            #pragma unroll
            for (int j = 0; j < 8; j++) {
                float t = r[i][j] * sc[j] + bi[j];
                v[j] = (MODE == 0) ? silu(t) : t;
            }
            float4* o0 = (float4*)&out[(size_t)p * C + bo + tx * 8];
            o0[0] = make_float4(v[0], v[1], v[2], v[3]);
            o0[1] = make_float4(v[4], v[5], v[6], v[7]);
        }
    } else if (MODE == 2) {
        float bi[8];
        #pragma unroll
        for (int j = 0; j < 8; j++) {
            int col = bo + tx * 8 + j;
            bi[j] = (col < 144) ? bias0[col] : (col < 216 ? bias1[col - 144] : 0.f);
        }
        const int c0 = bo + tx * 8;
        #pragma unroll
        for (int i = 0; i < 8; i++) {
            int p = bp + ty * 8 + i;
            if (c0 < 216)
                *(float4*)&out[(size_t)p * OMC + c0] =
                    make_float4(r[i][0] + bi[0], r[i][1] + bi[1],
                                r[i][2] + bi[2], r[i][3] + bi[3]);
            if (c0 + 4 < 216)
                *(float4*)&out[(size_t)p * OMC + c0 + 4] =
                    make_float4(r[i][4] + bi[4], r[i][5] + bi[5],
                                r[i][6] + bi[6], r[i][7] + bi[7]);
        }
    } else { // MODE 3: bias + BN2 + SiLU, NCHW out
        const int n = bp >> 12;
        const int hwb = (bp & 4095) + ty * 8;
        #pragma unroll
        for (int j = 0; j < 8; j++) {
            int o = bo + tx * 8 + j;
            float sc = bg[o] * rsqrtf(bv[o] + 1e-5f);
            float bi = bb[o] - bm[o] * sc + bias0[o] * sc;
            float v[8];
            #pragma unroll
            for (int i = 0; i < 8; i++) v[i] = silu(r[i][j] * sc + bi);
            float4* op = (float4*)&out[((size_t)(n * C + o)) * HW + hwb];
            op[0] = make_float4(v[0], v[1], v[2], v[3]);
            op[1] = make_float4(v[4], v[5], v[6], v[7]);
        }
    }
}

// ---------------------------------------------------------------------------
// Kernel 3: depthwise 3x3 conv(+bias) on y -> LayerNorm over C -> GELU(exact)
// one block (256 thr) per pixel
// ---------------------------------------------------------------------------
__global__ __launch_bounds__(256) void dwln_kernel(
    const float* __restrict__ y, const float* __restrict__ dww,
    const float* __restrict__ dwb, const float* __restrict__ lng,
    const float* __restrict__ lnb, float* __restrict__ z)
{
    const int p = blockIdx.x;
    const int c = threadIdx.x;
    const int n = p >> 12, hw = p & 4095;
    const int h = hw >> 6, w = hw & 63;

    float acc = dwb[c];
    #pragma unroll
    for (int ky = 0; ky < 3; ky++) {
        int hh = h + ky - 1;
        if (hh < 0 || hh > 63) continue;
        #pragma unroll
        for (int kx = 0; kx < 3; kx++) {
            int ww = w + kx - 1;
            if (ww < 0 || ww > 63) continue;
            acc += y[((size_t)(n << 12) + (hh << 6) + ww) * C + c] * dww[c * 9 + ky * 3 + kx];
        }
    }
    float s1 = acc, s2 = acc * acc;
    #pragma unroll
    for (int o = 16; o; o >>= 1) {
        s1 += __shfl_xor_sync(0xffffffffu, s1, o);
        s2 += __shfl_xor_sync(0xffffffffu, s2, o);
    }
    __shared__ float w1[8], w2[8];
    int warp = c >> 5, lane = c & 31;
    if (lane == 0) { w1[warp] = s1; w2[warp] = s2; }
    __syncthreads();
    if (warp == 0) {
        float a = lane < 8 ? w1[lane] : 0.f;
        float b = lane < 8 ? w2[lane] : 0.f;
        #pragma unroll
        for (int o = 4; o; o >>= 1) {
            a += __shfl_xor_sync(0xffffffffu, a, o);
            b += __shfl_xor_sync(0xffffffffu, b, o);
        }
        if (lane == 0) { w1[0] = a; w2[0] = b; }
    }
    __syncthreads();
    float mu = w1[0] * (1.f / 256.f);
    float var = w2[0] * (1.f / 256.f) - mu * mu;
    float zn = (acc - mu) * rsqrtf(var + 1e-5f) * lng[c] + lnb[c];
    float gl = 0.5f * zn * (1.f + erff(zn * 0.70710678118654752f));
    z[(size_t)p * C + c] = gl;
}

// ---------------------------------------------------------------------------
// Kernel 5: deformable sampling. Block = pixel (256 thr), warp = group.
// ---------------------------------------------------------------------------
__device__ __forceinline__ float samp(const float* __restrict__ xb, int yy, int xx)
{
    if (yy >= 1 && yy <= 64 && xx >= 1 && xx <= 64)
        return xb[((size_t)((yy - 1) << 6) + (xx - 1)) * C];
    return 0.f;
}

__global__ __launch_bounds__(256) void dcn_kernel(
    const float* __restrict__ xproj, const float* __restrict__ om,
    float* __restrict__ s)
{
    const int p = blockIdx.x;
    const int t = threadIdx.x;
    const int g = t >> 5, lane = t & 31;
    const int n = p >> 12, hw = p & 4095;
    const int h = hw >> 6, w = hw & 63;

    const float* offp = om + (size_t)p * OMC + g * 18;
    const float* mlp  = om + (size_t)p * OMC + 144 + g * 9;

    float ml[9];
    float mx = -1e30f;
    #pragma unroll
    for (int i = 0; i < 9; i++) { ml[i] = mlp[i]; mx = fmaxf(mx, ml[i]); }
    float se = 0.f;
    #pragma unroll
    for (int i = 0; i < 9; i++) { ml[i] = expf(ml[i] - mx); se += ml[i]; }
    float inv = 1.f / se;

    const int ch = g * 32 + lane;
    const float* xb = xproj + (size_t)n * HW * C + ch;
    float acc = 0.f;
    #pragma unroll
    for (int i = 0; i < 9; i++) {
        float px = (float)w + (float)(i / 3) + offp[2 * i];
        float py = (float)h + (float)(i % 3) + offp[2 * i + 1];
        float x0f = floorf(px), y0f = floorf(py);
        float wx = px - x0f, wy = py - y0f;
        int x0 = (int)x0f, y0 = (int)y0f;
        float v00 = samp(xb, y0,     x0);
        float v10 = samp(xb, y0,     x0 + 1);
        float v01 = samp(xb, y0 + 1, x0);
        float v11 = samp(xb, y0 + 1, x0 + 1);
        float bil = v00 * (1.f - wx) * (1.f - wy) + v10 * wx * (1.f - wy)
                  + v01 * (1.f - wx) * wy         + v11 * wx * wy;
        acc += ml[i] * inv * bil;
    }
    s[(size_t)p * C + ch] = acc;
}

// ---------------------------------------------------------------------------
extern "C" void kernel_launch(void* const* d_in, const int* in_sizes, int n_in,
                              void* d_out, int out_size)
{
    const float* x        = (const float*)d_in[0];
    const float* conv1_w  = (const float*)d_in[1];
    const float* bn1_g    = (const float*)d_in[2];
    const float* bn1_b    = (const float*)d_in[3];
    const float* bn1_m    = (const float*)d_in[4];
    const float* bn1_v    = (const float*)d_in[5];
    const float* inproj_w = (const float*)d_in[6];
    const float* inproj_b = (const float*)d_in[7];
    const float* dw_w     = (const float*)d_in[8];
    const float* dw_b     = (const float*)d_in[9];
    const float* ln_g     = (const float*)d_in[10];
    const float* ln_b     = (const float*)d_in[11];
    const float* off_w    = (const float*)d_in[12];
    const float* off_b    = (const float*)d_in[13];
    const float* mask_w   = (const float*)d_in[14];
    const float* mask_b   = (const float*)d_in[15];
    const float* outproj_w= (const float*)d_in[16];
    const float* outproj_b= (const float*)d_in[17];
    const float* bn2_g    = (const float*)d_in[18];
    const float* bn2_b    = (const float*)d_in[19];
    const float* bn2_m    = (const float*)d_in[20];
    const float* bn2_v    = (const float*)d_in[21];
    float* out = (float*)d_out;

    float *y, *xproj, *z, *om, *s;
    cudaGetSymbolAddress((void**)&y,     g_y);
    cudaGetSymbolAddress((void**)&xproj, g_xproj);
    cudaGetSymbolAddress((void**)&z,     g_z);
    cudaGetSymbolAddress((void**)&om,    g_om);
    cudaGetSymbolAddress((void**)&s,     g_s);

    dim3 grd(2, 64);   // 128 blocks: N tiles x M tiles

    gemm_k<0><<<grd, 256>>>(x, conv1_w, nullptr, nullptr, nullptr,
                            bn1_g, bn1_b, bn1_m, bn1_v, y);
    gemm_k<1><<<grd, 256>>>(y, inproj_w, nullptr, inproj_b, nullptr,
                            nullptr, nullptr, nullptr, nullptr, xproj);
    dwln_kernel<<<M, 256>>>(y, dw_w, dw_b, ln_g, ln_b, z);
    gemm_k<2><<<grd, 256>>>(z, off_w, mask_w, off_b, mask_b,
                            nullptr, nullptr, nullptr, nullptr, om);
    dcn_kernel<<<M, 256>>>(xproj, om, s);
    gemm_k<3><<<grd, 256>>>(s, outproj_w, nullptr, outproj_b, nullptr,
                            bn2_g, bn2_b, bn2_m, bn2_v, out);
}